// round 1
// baseline (speedup 1.0000x reference)
#include <cuda_runtime.h>

#define H 2048
#define S 2048
#define V 50257
#define CHUNKS 32

// ---- scratch (__device__ globals; no allocation allowed) ----
__device__ float g_attn_partial[CHUNKS * H];
__device__ float g_attn_applied[H];
__device__ float g_x[H];          // relu(comb output)
__device__ float g_gx[3 * H];     // x @ w_ih.T + b_ih
__device__ float g_gh[3 * H];     // h0 @ w_hh.T + b_hh
__device__ float g_hnew[H];
__device__ float g_logits[V];
__device__ float g_lse[1];        // max + log(sum exp)

__device__ __forceinline__ float warp_sum(float v) {
#pragma unroll
    for (int o = 16; o > 0; o >>= 1) v += __shfl_down_sync(0xffffffffu, v, o);
    return v;
}
__device__ __forceinline__ float warp_max(float v) {
#pragma unroll
    for (int o = 16; o > 0; o >>= 1) v = fmaxf(v, __shfl_down_sync(0xffffffffu, v, o));
    return v;
}

// ---- A: partial column sums of encoder_outputs (attn_weights are all 1.0) ----
__global__ void colsum_partial(const float* __restrict__ enc) {
    int col = blockIdx.x * 256 + threadIdx.x;          // 8 col-blocks
    int s0 = blockIdx.y * (S / CHUNKS);                // 32 row-chunks of 64
    float acc = 0.f;
#pragma unroll 8
    for (int s = 0; s < S / CHUNKS; ++s)
        acc += __ldg(&enc[(size_t)(s0 + s) * H + col]);
    g_attn_partial[blockIdx.y * H + col] = acc;
}

// ---- R: reduce partials -> attn_applied; also emit attn_weights (= 1.0) ----
__global__ void colsum_reduce(float* __restrict__ out_attn) {
    int h = blockIdx.x * 256 + threadIdx.x;
    float acc = 0.f;
#pragma unroll
    for (int c = 0; c < CHUNKS; ++c) acc += g_attn_partial[c * H + h];
    g_attn_applied[h] = acc;
    out_attn[h] = 1.0f;
}

// ---- B: x = relu( [embedded, attn_applied] @ comb_w.T + comb_b ) ----
__global__ void comb_relu(const float* __restrict__ comb_w,
                          const float* __restrict__ comb_b,
                          const float* __restrict__ emb,
                          const int* __restrict__ tok) {
    int warp = threadIdx.x >> 5, lane = threadIdx.x & 31;
    int h = blockIdx.x * 8 + warp;                     // 256 blocks x 8 warps = 2048 rows
    const float4* w4 = (const float4*)(comb_w + (size_t)h * (2 * H));
    const float4* e4 = (const float4*)(emb + (size_t)tok[0] * H);
    const float4* a4 = (const float4*)g_attn_applied;
    float acc = 0.f;
#pragma unroll
    for (int i = 0; i < 16; ++i) {                     // first 2048: embedded
        float4 wv = __ldg(&w4[i * 32 + lane]);
        float4 xv = __ldg(&e4[i * 32 + lane]);
        acc += wv.x * xv.x + wv.y * xv.y + wv.z * xv.z + wv.w * xv.w;
    }
    const float4* w2 = w4 + 512;
#pragma unroll
    for (int i = 0; i < 16; ++i) {                     // last 2048: attn_applied
        float4 wv = __ldg(&w2[i * 32 + lane]);
        float4 xv = a4[i * 32 + lane];
        acc += wv.x * xv.x + wv.y * xv.y + wv.z * xv.z + wv.w * xv.w;
    }
    acc = warp_sum(acc);
    if (lane == 0) g_x[h] = fmaxf(acc + comb_b[h], 0.f);
}

// ---- C: both GRU gate GEMVs in one kernel (rows 0..6143 = ih, 6144..12287 = hh) ----
__global__ void gates(const float* __restrict__ w_ih, const float* __restrict__ w_hh,
                      const float* __restrict__ b_ih, const float* __restrict__ b_hh,
                      const float* __restrict__ h0) {
    int warp = threadIdx.x >> 5, lane = threadIdx.x & 31;
    int row = blockIdx.x * 8 + warp;                   // 1536 blocks x 8 warps
    const float* w; const float* vec; const float* bias; float* dst; int r;
    if (row < 3 * H) { r = row;          w = w_ih; vec = g_x; bias = b_ih; dst = g_gx; }
    else             { r = row - 3 * H;  w = w_hh; vec = h0;  bias = b_hh; dst = g_gh; }
    const float4* w4 = (const float4*)(w + (size_t)r * H);
    const float4* v4 = (const float4*)vec;
    float acc = 0.f;
#pragma unroll
    for (int i = 0; i < 16; ++i) {
        float4 wv = __ldg(&w4[i * 32 + lane]);
        float4 xv = __ldg(&v4[i * 32 + lane]);
        acc += wv.x * xv.x + wv.y * xv.y + wv.z * xv.z + wv.w * xv.w;
    }
    acc = warp_sum(acc);
    if (lane == 0) dst[r] = acc + bias[r];
}

// ---- D: GRU nonlinearity -> h_new (also second output) ----
__global__ void gru_combine(const float* __restrict__ h0, float* __restrict__ out_h) {
    int h = blockIdx.x * 256 + threadIdx.x;
    float r = 1.f / (1.f + expf(-(g_gx[h] + g_gh[h])));
    float z = 1.f / (1.f + expf(-(g_gx[H + h] + g_gh[H + h])));
    float n = tanhf(g_gx[2 * H + h] + r * g_gh[2 * H + h]);
    float hn = (1.f - z) * n + z * h0[h];
    g_hnew[h] = hn;
    out_h[h] = hn;
}

// ---- E: the big GEMV: logits = h_new @ out_w.T + out_b (412 MB streamed) ----
__global__ void out_gemv(const float* __restrict__ out_w, const float* __restrict__ out_b) {
    __shared__ float4 hs[H / 4];
    for (int i = threadIdx.x; i < H / 4; i += 256)
        hs[i] = ((const float4*)g_hnew)[i];
    __syncthreads();
    int warp = threadIdx.x >> 5, lane = threadIdx.x & 31;
    int v = blockIdx.x * 8 + warp;
    if (v >= V) return;
    const float4* w4 = (const float4*)(out_w + (size_t)v * H);
    float acc = 0.f;
#pragma unroll
    for (int i = 0; i < 16; ++i) {
        float4 wv = __ldg(&w4[i * 32 + lane]);
        float4 xv = hs[i * 32 + lane];
        acc += wv.x * xv.x + wv.y * xv.y + wv.z * xv.z + wv.w * xv.w;
    }
    acc = warp_sum(acc);
    if (lane == 0) g_logits[v] = acc + out_b[v];
}

// ---- F1: single-block max + logsumexp over logits (L2-resident, 200 KB) ----
__global__ void lse_kernel() {
    __shared__ float red[32];
    __shared__ float red2[32];
    int t = threadIdx.x;
    float m = -1e30f;
    for (int i = t; i < V; i += 1024) m = fmaxf(m, g_logits[i]);
    m = warp_max(m);
    if ((t & 31) == 0) red[t >> 5] = m;
    __syncthreads();
    if (t < 32) {
        float mm = red[t];
        mm = warp_max(mm);
        if (t == 0) red[0] = mm;
    }
    __syncthreads();
    float M = red[0];
    float s = 0.f;
    for (int i = t; i < V; i += 1024) s += expf(g_logits[i] - M);
    s = warp_sum(s);
    if ((t & 31) == 0) red2[t >> 5] = s;
    __syncthreads();
    if (t == 0) {
        float ss = 0.f;
#pragma unroll
        for (int i = 0; i < 32; ++i) ss += red2[i];
        g_lse[0] = M + logf(ss);
    }
}

// ---- F2: write log_probs ----
__global__ void write_logprobs(float* __restrict__ out) {
    int v = blockIdx.x * 256 + threadIdx.x;
    if (v < V) out[v] = g_logits[v] - g_lse[0];
}

extern "C" void kernel_launch(void* const* d_in, const int* in_sizes, int n_in,
                              void* d_out, int out_size) {
    const int*   tok    = (const int*)d_in[0];
    const float* hidden = (const float*)d_in[1];   // (1,1,H)
    const float* enc    = (const float*)d_in[2];   // (S,H)
    const float* emb    = (const float*)d_in[3];   // (V,H)
    // d_in[4] attn_w, d_in[5] attn_b: dead code (softmax over singleton == 1)
    const float* comb_w = (const float*)d_in[6];
    const float* comb_b = (const float*)d_in[7];
    const float* w_ih   = (const float*)d_in[8];
    const float* w_hh   = (const float*)d_in[9];
    const float* b_ih   = (const float*)d_in[10];
    const float* b_hh   = (const float*)d_in[11];
    const float* out_w  = (const float*)d_in[12];
    const float* out_b  = (const float*)d_in[13];

    float* out      = (float*)d_out;
    float* out_h    = out + V;          // h_new
    float* out_attn = out + V + H;      // attn_weights (all ones)

    colsum_partial<<<dim3(8, 32), 256>>>(enc);
    colsum_reduce<<<8, 256>>>(out_attn);
    comb_relu<<<256, 256>>>(comb_w, comb_b, emb, tok);
    gates<<<1536, 256>>>(w_ih, w_hh, b_ih, b_hh, hidden);
    gru_combine<<<8, 256>>>(hidden, out_h);
    out_gemv<<<(V + 7) / 8, 256>>>(out_w, out_b);
    lse_kernel<<<1, 1024>>>();
    write_logprobs<<<(V + 255) / 256, 256>>>(out);
}